// round 7
// baseline (speedup 1.0000x reference)
#include <cuda_runtime.h>
#include <math.h>

#define NN    4096
#define NI_   1024
#define NB    8
#define NT    500
#define NWORD 128          // NN/32
#define SIM_CTAS 128       // 8 batches x 16 col-blocks (256 cols each)
#define SIM_TPB  128       // warps 0-1: E side, warps 2-3: I side; 4 cols/thread

// ---- device scratch ----
__device__ float     g_weff[(size_t)NN * NN];          // 64 MB
__device__ float     g_dff[(size_t)NT * NB * NN];      // 65.5 MB [t][b*N+j]
__device__ unsigned  g_mask[2][2][NB][NWORD];          // [buf][type][batch][word]
__device__ unsigned  g_cntB[NB * 32];                  // per-batch barrier counters (padded)

struct SimConsts {
    float ar[4], ad[4], omad[4], esyn[4];
    float dtt0, dtt1;
};

// ------------------------------------------------------------------
__global__ void init_kernel() {
    int idx = blockIdx.x * blockDim.x + threadIdx.x;
    if (idx < NB * 32) g_cntB[idx] = 0u;
    if (idx < 2 * NB * NWORD) ((unsigned*)g_mask[0])[idx] = 0u;
}

// ------------------------------------------------------------------
__global__ void weff_kernel(const float* __restrict__ W,
                            const float* __restrict__ scal,
                            const int*   __restrict__ ci) {
    int idx = blockIdx.x * 256 + threadIdx.x;          // float4 index
    int e = idx << 2;
    int i = e >> 12;
    int j = e & (NN - 1);
    float4 w = __ldg((const float4*)W + idx);
    int cri = __ldg(&ci[i]) * 2;
    float4 r;
    r.x = __fmul_rn(w.x, __ldg(&scal[cri + __ldg(&ci[j + 0])]));
    r.y = __fmul_rn(w.y, __ldg(&scal[cri + __ldg(&ci[j + 1])]));
    r.z = __fmul_rn(w.z, __ldg(&scal[cri + __ldg(&ci[j + 2])]));
    r.w = __fmul_rn(w.w, __ldg(&scal[cri + __ldg(&ci[j + 3])]));
    ((float4*)g_weff)[idx] = r;
}

// ------------------------------------------------------------------
// FF drive: active-row compaction + float4 row loads (unchanged).
// ------------------------------------------------------------------
__global__ void ff_kernel(const float* __restrict__ sp,
                          const float* __restrict__ wff,
                          const float* __restrict__ sff,
                          const int*   __restrict__ ciff,
                          const int*   __restrict__ ci) {
    __shared__ int    s_act[NI_];
    __shared__ float2 s_fv[NI_];
    __shared__ int    s_cnt[33];

    const int x   = blockIdx.x;
    const int t   = x >> 3;
    const int b   = x & 7;
    const int tid = threadIdx.x;
    const int lane = tid & 31;
    const int wrp  = tid >> 5;

    bool act[4]; int rnk[4];
#pragma unroll
    for (int r = 0; r < 4; ++r) {
        int i = r * 256 + tid;
        float sv = __ldg(&sp[((size_t)b * NT + t) * NI_ + i]);
        bool a = (sv != 0.0f);
        unsigned bal = __ballot_sync(0xffffffffu, a);
        if (lane == 0) s_cnt[r * 8 + wrp] = __popc(bal);
        act[r] = a;
        rnk[r] = __popc(bal & ((1u << lane) - 1u));
    }
    __syncthreads();
    if (tid == 0) {
        int run = 0;
#pragma unroll
        for (int s = 0; s < 32; ++s) { int c = s_cnt[s]; s_cnt[s] = run; run += c; }
        s_cnt[32] = run;
    }
    __syncthreads();
#pragma unroll
    for (int r = 0; r < 4; ++r) {
        if (act[r]) {
            int i = r * 256 + tid;
            int pos = s_cnt[r * 8 + wrp] + rnk[r];
            s_act[pos] = i << 10;
            int cf = __ldg(&ciff[i]) * 2;
            s_fv[pos] = make_float2(__ldg(&sff[cf]), __ldg(&sff[cf + 1]));
        }
    }
    __syncthreads();
    const int total = s_cnt[32];

    int4 ctq[4];
#pragma unroll
    for (int r = 0; r < 4; ++r) ctq[r] = __ldg((const int4*)ci + tid + 256 * r);

    float4 acc[4];
#pragma unroll
    for (int r = 0; r < 4; ++r) acc[r] = make_float4(0, 0, 0, 0);

    for (int k = 0; k < total; ++k) {
        int roff = s_act[k];
        float2 f = s_fv[k];
#pragma unroll
        for (int r = 0; r < 4; ++r) {
            float4 w4 = __ldg((const float4*)wff + roff + tid + 256 * r);
            acc[r].x = __fadd_rn(acc[r].x, __fmul_rn(w4.x, ctq[r].x ? f.y : f.x));
            acc[r].y = __fadd_rn(acc[r].y, __fmul_rn(w4.y, ctq[r].y ? f.y : f.x));
            acc[r].z = __fadd_rn(acc[r].z, __fmul_rn(w4.z, ctq[r].z ? f.y : f.x));
            acc[r].w = __fadd_rn(acc[r].w, __fmul_rn(w4.w, ctq[r].w ? f.y : f.x));
        }
    }
    size_t o = (size_t)x * (NN / 4);
#pragma unroll
    for (int r = 0; r < 4; ++r) ((float4*)g_dff)[o + tid + 256 * r] = acc[r];
}

// ------------------------------------------------------------------
// Persistent sim: rolling depth-32 dense gather, per-warp barrier poll,
// decoupled E-side publish path.
// ------------------------------------------------------------------
__global__ void __launch_bounds__(SIM_TPB, 1)
sim_kernel(const int* __restrict__ ci, float* __restrict__ out, SimConsts C) {
    __shared__ int           s_lstE[NN];
    __shared__ int           s_lstI[NN];
    __shared__ float         s_accI[256];
    __shared__ int           s_wsum[4];
    __shared__ unsigned char s_nibE[64];
    __shared__ unsigned char s_nibI[64];

    const int tid  = threadIdx.x;
    const int lane = tid & 31;
    const int wrp  = tid >> 5;
    const bool isE = (wrp < 2);
    const int q    = isE ? tid : (tid - 64);       // quad 0..63
    const int b    = blockIdx.x >> 4;
    const int jb   = (blockIdx.x & 15) << 8;
    const int j0   = jb + (q << 2);

    const int type = wrp >> 1;                     // list this warp builds
    const int half = wrp & 1;

    int ct[4]; float dtt[4], refst[4];
#pragma unroll
    for (int k = 0; k < 4; ++k) {
        ct[k]    = __ldg(&ci[j0 + k]);
        dtt[k]   = ct[k] ? C.dtt1 : C.dtt0;
        refst[k] = ct[k] ? 10.0f : 20.0f;
    }
    const float theta = -50.0f, u_reset = -65.0f, e_l = -70.0f, g_l = 10.0f;

    float v[4], ref[4], h0[4], h1[4], h2[4], h3[4], q0[4], q1[4], q2[4], q3[4];
#pragma unroll
    for (int k = 0; k < 4; ++k) {
        v[k] = e_l; ref[k] = 0.0f;
        h0[k] = h1[k] = h2[k] = h3[k] = 0.0f;
        q0[k] = q1[k] = q2[k] = q3[k] = 0.0f;
    }

    const float4* __restrict__ Wq = ((const float4*)g_weff) + (j0 >> 2);
    float* outp = out + ((size_t)b * NT) * NN + j0;
    const float* dffp = g_dff + (size_t)b * NN + j0;
    unsigned* cntp = &g_cntB[b * 32];

    float4 dff_cur = make_float4(0, 0, 0, 0), dff_next = dff_cur;
    if (isE) dff_cur = __ldg((const float4*)dffp);

    for (int t = 0; t < NT; ++t) {
        const int p = t & 1;

        // ---- 1. masks -> ascending compact lists (per type) ----
        unsigned w0 = __ldcg(&g_mask[p][type][b][half * 64 + lane]);
        unsigned w1 = __ldcg(&g_mask[p][type][b][half * 64 + 32 + lane]);
        int c0 = __popc(w0), c1 = __popc(w1);
        int s0 = c0, s1 = c1;
#pragma unroll
        for (int d = 1; d < 32; d <<= 1) {
            int t0 = __shfl_up_sync(0xffffffffu, s0, d);
            int t1 = __shfl_up_sync(0xffffffffu, s1, d);
            if (lane >= d) { s0 += t0; s1 += t1; }
        }
        int tot0    = __shfl_sync(0xffffffffu, s0, 31);
        int tothalf = tot0 + __shfl_sync(0xffffffffu, s1, 31);
        if (lane == 31) s_wsum[wrp] = tothalf;
        __syncthreads();
        const int totE = s_wsum[0] + s_wsum[1];
        const int totI = s_wsum[2] + s_wsum[3];
        {
            int base_half = half ? s_wsum[type * 2] : 0;
            int* dst = type ? s_lstI : s_lstE;
            int pos = base_half + s0 - c0;
            int ib  = (half * 64 + lane) << 5;
            unsigned m = w0;
            while (m) {
                int bit = __ffs(m) - 1; m &= m - 1;
                dst[pos++] = (ib + bit) << 10;          // i * 1024 (float4 stride)
            }
            pos = base_half + tot0 + s1 - c1;
            ib  = (half * 64 + 32 + lane) << 5;
            m = w1;
            while (m) {
                int bit = __ffs(m) - 1; m &= m - 1;
                dst[pos++] = (ib + bit) << 10;
            }
        }
        __syncthreads();

        if (isE && t + 1 < NT)
            dff_next = __ldg((const float4*)(dffp + (size_t)(t + 1) * (NB * NN)));

        // ---- 2. dense float4 gather, rolling depth-32 ----
        const int  tot = isE ? totE : totI;
        const int* lst = isE ? s_lstE : s_lstI;
        const float4 Z4 = make_float4(0, 0, 0, 0);
        float a0 = 0.0f, a1 = 0.0f, a2 = 0.0f, a3 = 0.0f;
        {
            float4 buf[32];
#pragma unroll
            for (int u = 0; u < 32; ++u)
                buf[u] = (u < tot) ? __ldg(Wq + lst[u]) : Z4;
            for (int base = 0; base < tot; base += 32) {
#pragma unroll
                for (int u = 0; u < 32; ++u) {
                    float4 val = buf[u];
                    int k = base + 32 + u;
                    buf[u] = (k < tot) ? __ldg(Wq + lst[k]) : Z4;
                    a0 = __fadd_rn(a0, val.x);
                    a1 = __fadd_rn(a1, val.y);
                    a2 = __fadd_rn(a2, val.z);
                    a3 = __fadd_rn(a3, val.w);
                }
            }
        }
        if (!isE) {
            s_accI[q * 4 + 0] = a0; s_accI[q * 4 + 1] = a1;
            s_accI[q * 4 + 2] = a2; s_accI[q * 4 + 3] = a3;
        }
        __syncthreads();

        // ---- 3. membrane update (E threads own state for 4 neurons) ----
        if (isE) {
            float acc_e[4] = {a0, a1, a2, a3};
            float dffv[4]  = {dff_cur.x, dff_cur.y, dff_cur.z, dff_cur.w};
            float sn[4];
            unsigned nibE = 0, nibI = 0;
#pragma unroll
            for (int k = 0; k < 4; ++k) {
                float acc_i = s_accI[q * 4 + k];
                h0[k] = __fmaf_rn(h0[k], C.ar[0], acc_e[k]);
                h1[k] = __fmaf_rn(h1[k], C.ar[1], __fmul_rn(acc_e[k], 0.5f));
                h2[k] = __fmaf_rn(h2[k], C.ar[2], acc_i);
                h3[k] = __fmaf_rn(h3[k], C.ar[3], dffv[k]);
                q0[k] = __fmaf_rn(q0[k], C.ad[0], __fmul_rn(C.omad[0], h0[k]));
                q1[k] = __fmaf_rn(q1[k], C.ad[1], __fmul_rn(C.omad[1], h1[k]));
                q2[k] = __fmaf_rn(q2[k], C.ad[2], __fmul_rn(C.omad[2], h2[k]));
                q3[k] = __fmaf_rn(q3[k], C.ad[3], __fmul_rn(C.omad[3], h3[k]));

                float I = __fmul_rn(q0[k], __fsub_rn(C.esyn[0], v[k]));
                I = __fadd_rn(I, __fmul_rn(q1[k], __fsub_rn(C.esyn[1], v[k])));
                I = __fadd_rn(I, __fmul_rn(q2[k], __fsub_rn(C.esyn[2], v[k])));
                I = __fadd_rn(I, __fmul_rn(q3[k], __fsub_rn(C.esyn[3], v[k])));

                float vn = __fmaf_rn(dtt[k],
                                     __fadd_rn(__fsub_rn(e_l, v[k]),
                                               __fdiv_rn(I, g_l)),
                                     v[k]);
                bool refr = (ref[k] > 0.0f);
                if (refr) vn = u_reset;
                bool spk = (!refr) && (vn > theta);
                sn[k]  = spk ? 1.0f : 0.0f;
                v[k]   = spk ? u_reset : vn;
                ref[k] = spk ? refst[k] : fmaxf(__fsub_rn(ref[k], 1.0f), 0.0f);
                unsigned bit = spk ? (1u << k) : 0u;
                if (ct[k] == 0) nibE |= bit; else nibI |= bit;
            }
            s_nibE[q] = (unsigned char)nibE;
            s_nibI[q] = (unsigned char)nibI;
            *(float4*)(outp + (size_t)t * NN) = make_float4(sn[0], sn[1], sn[2], sn[3]);

            // ---- 4. E-side publish path (named barrier, I-warps skip) ----
            if (t != NT - 1) {
                asm volatile("bar.sync 1, 64;" ::: "memory");
                if (tid < 8) {
                    unsigned we = 0, wi = 0;
#pragma unroll
                    for (int k = 0; k < 8; ++k) {
                        we |= ((unsigned)s_nibE[tid * 8 + k]) << (4 * k);
                        wi |= ((unsigned)s_nibI[tid * 8 + k]) << (4 * k);
                    }
                    const int qb = p ^ 1;
                    const int word = (jb >> 5) + tid;
                    g_mask[qb][0][b][word] = we;
                    g_mask[qb][1][b][word] = wi;
                    // own release orders own two stores; 8 arrivals per CTA
                    asm volatile("red.release.gpu.global.add.u32 [%0], %1;"
                                 :: "l"(cntp), "r"(1u) : "memory");
                }
            }
        }
        dff_cur = dff_next;

        // ---- 5. per-warp barrier poll (128 arrivals per batch per step) ----
        if (t != NT - 1) {
            const unsigned target = 128u * (unsigned)(t + 1);
            if (lane == 0) {
                unsigned cv;
                do {
                    asm volatile("ld.acquire.gpu.global.u32 %0, [%1];"
                                 : "=r"(cv) : "l"(cntp));
                } while (cv < target);
            }
            __syncwarp();
        }
    }
}

// ------------------------------------------------------------------
extern "C" void kernel_launch(void* const* d_in, const int* in_sizes, int n_in,
                              void* d_out, int out_size) {
    const float* in_spikes = (const float*)d_in[0];
    const float* weights   = (const float*)d_in[1];
    const float* wff       = (const float*)d_in[2];
    const float* scal      = (const float*)d_in[3];
    const float* scalff    = (const float*)d_in[4];
    const int*   ci        = (const int*)  d_in[5];
    const int*   ciff      = (const int*)  d_in[6];
    float*       out       = (float*)d_out;

    const float tau_rise[4]  = {0.5f, 2.0f, 0.5f, 0.5f};
    const float tau_decay[4] = {2.0f, 100.0f, 5.0f, 2.0f};
    SimConsts C;
    for (int s = 0; s < 4; ++s) {
        float qr = -(0.1f / tau_rise[s]);
        float qd = -(0.1f / tau_decay[s]);
        C.ar[s]   = (float)exp((double)qr);
        C.ad[s]   = (float)exp((double)qd);
        C.omad[s] = 1.0f - C.ad[s];
    }
    C.esyn[0] = 0.0f; C.esyn[1] = 0.0f; C.esyn[2] = -80.0f; C.esyn[3] = 0.0f;
    C.dtt0 = 0.1f / 20.0f;
    C.dtt1 = 0.1f / 10.0f;

    init_kernel<<<8, 256>>>();
    weff_kernel<<<(NN * NN / 4) / 256, 256>>>(weights, scal, ci);
    ff_kernel<<<NT * NB, 256>>>(in_spikes, wff, scalff, ciff, ci);
    sim_kernel<<<SIM_CTAS, SIM_TPB>>>(ci, out, C);
}

// round 8
// speedup vs baseline: 1.2195x; 1.2195x over previous
#include <cuda_runtime.h>
#include <math.h>

#define NN    4096
#define NI_   1024
#define NB    8
#define NT    500
#define NWORD 128          // NN/32
#define SIM_CTAS 128       // 8 batches x 16 col-blocks (256 cols each)
#define SIM_TPB  128       // warps 0-1: E side, warps 2-3: I side; 4 cols/thread

// ---- device scratch ----
__device__ float     g_weff[(size_t)NN * NN];          // 64 MB
__device__ float     g_dff[(size_t)NT * NB * NN];      // 65.5 MB [t][b*N+j]
__device__ unsigned  g_mask[2][2][NB][NWORD];          // [buf][type][batch][word]
__device__ unsigned  g_cntB[NB * 32];                  // per-batch barrier counters (padded)

struct SimConsts {
    float ar[4], ad[4], omad[4], esyn[4];
    float dtt0, dtt1;
};

// ------------------------------------------------------------------
__global__ void init_kernel() {
    int idx = blockIdx.x * blockDim.x + threadIdx.x;
    if (idx < NB * 32) g_cntB[idx] = 0u;
    if (idx < 2 * NB * NWORD) ((unsigned*)g_mask[0])[idx] = 0u;
}

// ------------------------------------------------------------------
__global__ void weff_kernel(const float* __restrict__ W,
                            const float* __restrict__ scal,
                            const int*   __restrict__ ci) {
    int idx = blockIdx.x * 256 + threadIdx.x;          // float4 index
    int e = idx << 2;
    int i = e >> 12;
    int j = e & (NN - 1);
    float4 w = __ldg((const float4*)W + idx);
    int cri = __ldg(&ci[i]) * 2;
    float4 r;
    r.x = __fmul_rn(w.x, __ldg(&scal[cri + __ldg(&ci[j + 0])]));
    r.y = __fmul_rn(w.y, __ldg(&scal[cri + __ldg(&ci[j + 1])]));
    r.z = __fmul_rn(w.z, __ldg(&scal[cri + __ldg(&ci[j + 2])]));
    r.w = __fmul_rn(w.w, __ldg(&scal[cri + __ldg(&ci[j + 3])]));
    ((float4*)g_weff)[idx] = r;
}

// ------------------------------------------------------------------
// FF drive: active-row compaction + float4 row loads (unchanged).
// ------------------------------------------------------------------
__global__ void ff_kernel(const float* __restrict__ sp,
                          const float* __restrict__ wff,
                          const float* __restrict__ sff,
                          const int*   __restrict__ ciff,
                          const int*   __restrict__ ci) {
    __shared__ int    s_act[NI_];
    __shared__ float2 s_fv[NI_];
    __shared__ int    s_cnt[33];

    const int x   = blockIdx.x;
    const int t   = x >> 3;
    const int b   = x & 7;
    const int tid = threadIdx.x;
    const int lane = tid & 31;
    const int wrp  = tid >> 5;

    bool act[4]; int rnk[4];
#pragma unroll
    for (int r = 0; r < 4; ++r) {
        int i = r * 256 + tid;
        float sv = __ldg(&sp[((size_t)b * NT + t) * NI_ + i]);
        bool a = (sv != 0.0f);
        unsigned bal = __ballot_sync(0xffffffffu, a);
        if (lane == 0) s_cnt[r * 8 + wrp] = __popc(bal);
        act[r] = a;
        rnk[r] = __popc(bal & ((1u << lane) - 1u));
    }
    __syncthreads();
    if (tid == 0) {
        int run = 0;
#pragma unroll
        for (int s = 0; s < 32; ++s) { int c = s_cnt[s]; s_cnt[s] = run; run += c; }
        s_cnt[32] = run;
    }
    __syncthreads();
#pragma unroll
    for (int r = 0; r < 4; ++r) {
        if (act[r]) {
            int i = r * 256 + tid;
            int pos = s_cnt[r * 8 + wrp] + rnk[r];
            s_act[pos] = i << 10;
            int cf = __ldg(&ciff[i]) * 2;
            s_fv[pos] = make_float2(__ldg(&sff[cf]), __ldg(&sff[cf + 1]));
        }
    }
    __syncthreads();
    const int total = s_cnt[32];

    int4 ctq[4];
#pragma unroll
    for (int r = 0; r < 4; ++r) ctq[r] = __ldg((const int4*)ci + tid + 256 * r);

    float4 acc[4];
#pragma unroll
    for (int r = 0; r < 4; ++r) acc[r] = make_float4(0, 0, 0, 0);

    for (int k = 0; k < total; ++k) {
        int roff = s_act[k];
        float2 f = s_fv[k];
#pragma unroll
        for (int r = 0; r < 4; ++r) {
            float4 w4 = __ldg((const float4*)wff + roff + tid + 256 * r);
            acc[r].x = __fadd_rn(acc[r].x, __fmul_rn(w4.x, ctq[r].x ? f.y : f.x));
            acc[r].y = __fadd_rn(acc[r].y, __fmul_rn(w4.y, ctq[r].y ? f.y : f.x));
            acc[r].z = __fadd_rn(acc[r].z, __fmul_rn(w4.z, ctq[r].z ? f.y : f.x));
            acc[r].w = __fadd_rn(acc[r].w, __fmul_rn(w4.w, ctq[r].w ? f.y : f.x));
        }
    }
    size_t o = (size_t)x * (NN / 4);
#pragma unroll
    for (int r = 0; r < 4; ++r) ((float4*)g_dff)[o + tid + 256 * r] = acc[r];
}

// ------------------------------------------------------------------
// Persistent sim: R6 depth-16 double-buffer gather (no spill) +
// E-only publish path + per-warp barrier poll.
// ------------------------------------------------------------------
__global__ void __launch_bounds__(SIM_TPB, 1)
sim_kernel(const int* __restrict__ ci, float* __restrict__ out, SimConsts C) {
    __shared__ int           s_lstE[NN];
    __shared__ int           s_lstI[NN];
    __shared__ float         s_accI[256];
    __shared__ int           s_wsum[4];
    __shared__ unsigned char s_nibE[64];
    __shared__ unsigned char s_nibI[64];

    const int tid  = threadIdx.x;
    const int lane = tid & 31;
    const int wrp  = tid >> 5;
    const bool isE = (wrp < 2);
    const int q    = isE ? tid : (tid - 64);       // quad 0..63
    const int b    = blockIdx.x >> 4;
    const int jb   = (blockIdx.x & 15) << 8;
    const int j0   = jb + (q << 2);

    const int type = wrp >> 1;                     // list this warp builds
    const int half = wrp & 1;

    int ct[4]; float dtt[4], refst[4];
#pragma unroll
    for (int k = 0; k < 4; ++k) {
        ct[k]    = __ldg(&ci[j0 + k]);
        dtt[k]   = ct[k] ? C.dtt1 : C.dtt0;
        refst[k] = ct[k] ? 10.0f : 20.0f;
    }
    const float theta = -50.0f, u_reset = -65.0f, e_l = -70.0f, g_l = 10.0f;

    float v[4], ref[4], h0[4], h1[4], h2[4], h3[4], q0[4], q1[4], q2[4], q3[4];
#pragma unroll
    for (int k = 0; k < 4; ++k) {
        v[k] = e_l; ref[k] = 0.0f;
        h0[k] = h1[k] = h2[k] = h3[k] = 0.0f;
        q0[k] = q1[k] = q2[k] = q3[k] = 0.0f;
    }

    const float4* __restrict__ Wq = ((const float4*)g_weff) + (j0 >> 2);
    float* outp = out + ((size_t)b * NT) * NN + j0;
    const float* dffp = g_dff + (size_t)b * NN + j0;
    unsigned* cntp = &g_cntB[b * 32];

    float4 dff_cur = make_float4(0, 0, 0, 0), dff_next = dff_cur;
    if (isE) dff_cur = __ldg((const float4*)dffp);

    for (int t = 0; t < NT; ++t) {
        const int p = t & 1;

        // ---- 1. masks -> ascending compact lists (per type) ----
        unsigned w0 = __ldcg(&g_mask[p][type][b][half * 64 + lane]);
        unsigned w1 = __ldcg(&g_mask[p][type][b][half * 64 + 32 + lane]);
        int c0 = __popc(w0), c1 = __popc(w1);
        int s0 = c0, s1 = c1;
#pragma unroll
        for (int d = 1; d < 32; d <<= 1) {
            int t0 = __shfl_up_sync(0xffffffffu, s0, d);
            int t1 = __shfl_up_sync(0xffffffffu, s1, d);
            if (lane >= d) { s0 += t0; s1 += t1; }
        }
        int tot0    = __shfl_sync(0xffffffffu, s0, 31);
        int tothalf = tot0 + __shfl_sync(0xffffffffu, s1, 31);
        if (lane == 31) s_wsum[wrp] = tothalf;
        __syncthreads();
        const int totE = s_wsum[0] + s_wsum[1];
        const int totI = s_wsum[2] + s_wsum[3];
        {
            int base_half = half ? s_wsum[type * 2] : 0;
            int* dst = type ? s_lstI : s_lstE;
            int pos = base_half + s0 - c0;
            int ib  = (half * 64 + lane) << 5;
            unsigned m = w0;
            while (m) {
                int bit = __ffs(m) - 1; m &= m - 1;
                dst[pos++] = (ib + bit) << 10;          // i * 1024 (float4 stride)
            }
            pos = base_half + tot0 + s1 - c1;
            ib  = (half * 64 + 32 + lane) << 5;
            m = w1;
            while (m) {
                int bit = __ffs(m) - 1; m &= m - 1;
                dst[pos++] = (ib + bit) << 10;
            }
        }
        __syncthreads();

        if (isE && t + 1 < NT)
            dff_next = __ldg((const float4*)(dffp + (size_t)(t + 1) * (NB * NN)));

        // ---- 2. dense float4 gather, depth-16 double buffer (R6) ----
        const int  tot = isE ? totE : totI;
        const int* lst = isE ? s_lstE : s_lstI;
        const float4 Z4 = make_float4(0, 0, 0, 0);
        float a0 = 0.0f, a1 = 0.0f, a2 = 0.0f, a3 = 0.0f;
        {
            float4 bA[16], bB[16];
#pragma unroll
            for (int u = 0; u < 16; ++u)
                bA[u] = (u < tot) ? __ldg(Wq + lst[u]) : Z4;
            for (int base = 0; base < tot; base += 32) {
#pragma unroll
                for (int u = 0; u < 16; ++u) {
                    int k = base + 16 + u;
                    bB[u] = (k < tot) ? __ldg(Wq + lst[k]) : Z4;
                }
#pragma unroll
                for (int u = 0; u < 16; ++u) {
                    a0 = __fadd_rn(a0, bA[u].x);
                    a1 = __fadd_rn(a1, bA[u].y);
                    a2 = __fadd_rn(a2, bA[u].z);
                    a3 = __fadd_rn(a3, bA[u].w);
                }
#pragma unroll
                for (int u = 0; u < 16; ++u) {
                    int k = base + 32 + u;
                    bA[u] = (k < tot) ? __ldg(Wq + lst[k]) : Z4;
                }
#pragma unroll
                for (int u = 0; u < 16; ++u) {
                    a0 = __fadd_rn(a0, bB[u].x);
                    a1 = __fadd_rn(a1, bB[u].y);
                    a2 = __fadd_rn(a2, bB[u].z);
                    a3 = __fadd_rn(a3, bB[u].w);
                }
            }
        }
        if (!isE) {
            s_accI[q * 4 + 0] = a0; s_accI[q * 4 + 1] = a1;
            s_accI[q * 4 + 2] = a2; s_accI[q * 4 + 3] = a3;
        }
        __syncthreads();

        // ---- 3. membrane update (E threads own state for 4 neurons) ----
        if (isE) {
            float acc_e[4] = {a0, a1, a2, a3};
            float dffv[4]  = {dff_cur.x, dff_cur.y, dff_cur.z, dff_cur.w};
            float sn[4];
            unsigned nibE = 0, nibI = 0;
#pragma unroll
            for (int k = 0; k < 4; ++k) {
                float acc_i = s_accI[q * 4 + k];
                h0[k] = __fmaf_rn(h0[k], C.ar[0], acc_e[k]);
                h1[k] = __fmaf_rn(h1[k], C.ar[1], __fmul_rn(acc_e[k], 0.5f));
                h2[k] = __fmaf_rn(h2[k], C.ar[2], acc_i);
                h3[k] = __fmaf_rn(h3[k], C.ar[3], dffv[k]);
                q0[k] = __fmaf_rn(q0[k], C.ad[0], __fmul_rn(C.omad[0], h0[k]));
                q1[k] = __fmaf_rn(q1[k], C.ad[1], __fmul_rn(C.omad[1], h1[k]));
                q2[k] = __fmaf_rn(q2[k], C.ad[2], __fmul_rn(C.omad[2], h2[k]));
                q3[k] = __fmaf_rn(q3[k], C.ad[3], __fmul_rn(C.omad[3], h3[k]));

                float I = __fmul_rn(q0[k], __fsub_rn(C.esyn[0], v[k]));
                I = __fadd_rn(I, __fmul_rn(q1[k], __fsub_rn(C.esyn[1], v[k])));
                I = __fadd_rn(I, __fmul_rn(q2[k], __fsub_rn(C.esyn[2], v[k])));
                I = __fadd_rn(I, __fmul_rn(q3[k], __fsub_rn(C.esyn[3], v[k])));

                float vn = __fmaf_rn(dtt[k],
                                     __fadd_rn(__fsub_rn(e_l, v[k]),
                                               __fdiv_rn(I, g_l)),
                                     v[k]);
                bool refr = (ref[k] > 0.0f);
                if (refr) vn = u_reset;
                bool spk = (!refr) && (vn > theta);
                sn[k]  = spk ? 1.0f : 0.0f;
                v[k]   = spk ? u_reset : vn;
                ref[k] = spk ? refst[k] : fmaxf(__fsub_rn(ref[k], 1.0f), 0.0f);
                unsigned bit = spk ? (1u << k) : 0u;
                if (ct[k] == 0) nibE |= bit; else nibI |= bit;
            }
            s_nibE[q] = (unsigned char)nibE;
            s_nibI[q] = (unsigned char)nibI;
            *(float4*)(outp + (size_t)t * NN) = make_float4(sn[0], sn[1], sn[2], sn[3]);

            // ---- 4. E-only publish path (named barrier; I-warps skip) ----
            if (t != NT - 1) {
                asm volatile("bar.sync 1, 64;" ::: "memory");
                if (tid < 8) {
                    unsigned we = 0, wi = 0;
#pragma unroll
                    for (int k = 0; k < 8; ++k) {
                        we |= ((unsigned)s_nibE[tid * 8 + k]) << (4 * k);
                        wi |= ((unsigned)s_nibI[tid * 8 + k]) << (4 * k);
                    }
                    const int qb = p ^ 1;
                    const int word = (jb >> 5) + tid;
                    g_mask[qb][0][b][word] = we;
                    g_mask[qb][1][b][word] = wi;
                    // own release orders own two stores; 8 arrivals per CTA
                    asm volatile("red.release.gpu.global.add.u32 [%0], %1;"
                                 :: "l"(cntp), "r"(1u) : "memory");
                }
            }
        }
        dff_cur = dff_next;

        // ---- 5. per-warp barrier poll (128 arrivals per batch per step) ----
        if (t != NT - 1) {
            const unsigned target = 128u * (unsigned)(t + 1);
            if (lane == 0) {
                unsigned cv;
                do {
                    asm volatile("ld.acquire.gpu.global.u32 %0, [%1];"
                                 : "=r"(cv) : "l"(cntp));
                } while (cv < target);
            }
            __syncwarp();
        }
    }
}

// ------------------------------------------------------------------
extern "C" void kernel_launch(void* const* d_in, const int* in_sizes, int n_in,
                              void* d_out, int out_size) {
    const float* in_spikes = (const float*)d_in[0];
    const float* weights   = (const float*)d_in[1];
    const float* wff       = (const float*)d_in[2];
    const float* scal      = (const float*)d_in[3];
    const float* scalff    = (const float*)d_in[4];
    const int*   ci        = (const int*)  d_in[5];
    const int*   ciff      = (const int*)  d_in[6];
    float*       out       = (float*)d_out;

    const float tau_rise[4]  = {0.5f, 2.0f, 0.5f, 0.5f};
    const float tau_decay[4] = {2.0f, 100.0f, 5.0f, 2.0f};
    SimConsts C;
    for (int s = 0; s < 4; ++s) {
        float qr = -(0.1f / tau_rise[s]);
        float qd = -(0.1f / tau_decay[s]);
        C.ar[s]   = (float)exp((double)qr);
        C.ad[s]   = (float)exp((double)qd);
        C.omad[s] = 1.0f - C.ad[s];
    }
    C.esyn[0] = 0.0f; C.esyn[1] = 0.0f; C.esyn[2] = -80.0f; C.esyn[3] = 0.0f;
    C.dtt0 = 0.1f / 20.0f;
    C.dtt1 = 0.1f / 10.0f;

    init_kernel<<<8, 256>>>();
    weff_kernel<<<(NN * NN / 4) / 256, 256>>>(weights, scal, ci);
    ff_kernel<<<NT * NB, 256>>>(in_spikes, wff, scalff, ciff, ci);
    sim_kernel<<<SIM_CTAS, SIM_TPB>>>(ci, out, C);
}